// round 1
// baseline (speedup 1.0000x reference)
#include <cuda_runtime.h>
#include <cuda_bf16.h>
#include <math.h>

// Problem constants
#define HID   2048
#define NHEADS 16
#define HDIM  128
#define BATCH 2
#define SEQ   2048
#define MTOT  (BATCH*SEQ)   // 4096

// ---------------------------------------------------------------------------
// Scratch (device globals: allocation-free)
// ---------------------------------------------------------------------------
__device__ float g_q  [(size_t)MTOT * HID];   // [B,NH,S,HD]
__device__ float g_k  [(size_t)MTOT * HID];   // [B,NH,S,HD]
__device__ float g_v  [(size_t)MTOT * HID];   // [B,NH,S,HD]
__device__ float g_ctx[(size_t)MTOT * HID];   // [B,S,H]

// ---------------------------------------------------------------------------
// NT SGEMM with bias:  C[m,n] = sum_k A[m,k]*B[n,k] + bias[n]
// A: [M,K] row-major, B: [N,K] row-major (i.e. x @ W.T + b for torch Linear)
// SCATTER=true writes C into [B,NH,S,HD] layout (m=b*SEQ+s, n=h*HDIM+d)
// Tiles: BM=128, BN=128, BK=16; 256 threads; 8x8 per-thread micro-tile.
// ---------------------------------------------------------------------------
template<bool SCATTER>
__global__ void __launch_bounds__(256)
gemm_nt_bias(const float* __restrict__ A,
             const float* __restrict__ B,
             const float* __restrict__ bias,
             float* __restrict__ C,
             int M, int N, int K)
{
    constexpr int BM = 128, BN = 128, BK = 16;
    __shared__ float As[BK][BM + 4];
    __shared__ float Bs[BK][BN + 4];

    const int tid = threadIdx.x;
    const int block_m = blockIdx.y * BM;
    const int block_n = blockIdx.x * BN;

    const int tr = tid >> 4;   // 0..15 (row group)
    const int tc = tid & 15;   // 0..15 (col group)

    // global-load mapping: 128 rows x 4 float4 per tile = 512 float4; 2 per thread
    const int lr  = tid >> 2;  // 0..63
    const int lc4 = tid & 3;   // 0..3 -> k offset lc4*4

    const float* Aptr = A + (size_t)block_m * K;
    const float* Bptr = B + (size_t)block_n * K;

    float acc[8][8];
#pragma unroll
    for (int i = 0; i < 8; ++i)
#pragma unroll
        for (int j = 0; j < 8; ++j) acc[i][j] = 0.f;

    for (int k0 = 0; k0 < K; k0 += BK) {
#pragma unroll
        for (int it = 0; it < 2; ++it) {
            int r = lr + it * 64;
            float4 a = *(const float4*)(Aptr + (size_t)r * K + k0 + lc4 * 4);
            As[lc4 * 4 + 0][r] = a.x;
            As[lc4 * 4 + 1][r] = a.y;
            As[lc4 * 4 + 2][r] = a.z;
            As[lc4 * 4 + 3][r] = a.w;
            float4 b = *(const float4*)(Bptr + (size_t)r * K + k0 + lc4 * 4);
            Bs[lc4 * 4 + 0][r] = b.x;
            Bs[lc4 * 4 + 1][r] = b.y;
            Bs[lc4 * 4 + 2][r] = b.z;
            Bs[lc4 * 4 + 3][r] = b.w;
        }
        __syncthreads();

#pragma unroll
        for (int kk = 0; kk < BK; ++kk) {
            float a[8], b[8];
#pragma unroll
            for (int i = 0; i < 8; ++i) a[i] = As[kk][tr * 8 + i];
#pragma unroll
            for (int j = 0; j < 8; ++j) b[j] = Bs[kk][tc * 8 + j];
#pragma unroll
            for (int i = 0; i < 8; ++i)
#pragma unroll
                for (int j = 0; j < 8; ++j)
                    acc[i][j] = fmaf(a[i], b[j], acc[i][j]);
        }
        __syncthreads();
    }

#pragma unroll
    for (int i = 0; i < 8; ++i) {
        int m = block_m + tr * 8 + i;
#pragma unroll
        for (int j = 0; j < 8; ++j) {
            int n = block_n + tc * 8 + j;
            float v = acc[i][j] + bias[n];
            if (!SCATTER) {
                C[(size_t)m * N + n] = v;
            } else {
                int b = m / SEQ, s = m - b * SEQ;
                int h = n >> 7, d = n & 127;   // HDIM = 128
                C[(((size_t)b * NHEADS + h) * SEQ + s) * HDIM + d] = v;
            }
        }
    }
}

// ---------------------------------------------------------------------------
// Flash attention (fp32, online softmax).
// grid: (SEQ/TQ, BATCH*NHEADS), block 256.
// Thread t: qi = t>>2 (query within tile), quad = t&3 (32 d-dims).
// K/V tiles in smem with quad-swizzled layout: stride QSTRIDE=TK*32+8 floats
// between d-quads so the 4 quads of a warp hit distinct banks.
// Output written directly into [B,S,H] layout for the final projection.
// ---------------------------------------------------------------------------
#define TQ 64
#define TK 32
#define QSTRIDE (TK * 32 + 8)   // 1032 floats; quad stride % 32 == 8 -> conflict-free

__global__ void __launch_bounds__(256)
attn_kernel(const float* __restrict__ Q,
            const float* __restrict__ K,
            const float* __restrict__ V,
            float* __restrict__ O)
{
    __shared__ float Ks[4 * QSTRIDE];
    __shared__ float Vs[4 * QSTRIDE];

    const int bh = blockIdx.y;            // 0..B*NH-1
    const int b  = bh / NHEADS;
    const int h  = bh - b * NHEADS;
    const int q0 = blockIdx.x * TQ;

    const int tid  = threadIdx.x;
    const int qi   = tid >> 2;            // 0..63
    const int quad = tid & 3;             // 0..3

    const float* Qb = Q + (size_t)bh * SEQ * HDIM;
    const float* Kb = K + (size_t)bh * SEQ * HDIM;
    const float* Vb = V + (size_t)bh * SEQ * HDIM;

    // load this thread's q slice (32 dims), pre-scaled by 1/sqrt(HDIM)
    const float scale = 0.08838834764831845f;  // 1/sqrt(128)
    float qreg[32];
    {
        const float* qrow = Qb + (size_t)(q0 + qi) * HDIM + quad * 32;
#pragma unroll
        for (int i = 0; i < 32; i += 4) {
            float4 t = *(const float4*)(qrow + i);
            qreg[i + 0] = t.x * scale;
            qreg[i + 1] = t.y * scale;
            qreg[i + 2] = t.z * scale;
            qreg[i + 3] = t.w * scale;
        }
    }

    float acc[32];
#pragma unroll
    for (int i = 0; i < 32; ++i) acc[i] = 0.f;
    float m_i = -1e30f;
    float l_i = 0.f;

    for (int k0 = 0; k0 < SEQ; k0 += TK) {
        __syncthreads();  // protect previous tile's reads
        // cooperative load of K/V tile into swizzled smem
        for (int f = tid; f < TK * 32; f += 256) {
            int j  = f >> 5;            // key row 0..TK-1
            int d4 = (f & 31) * 4;      // d offset 0..124
            int idx = (d4 >> 5) * QSTRIDE + j * 32 + (d4 & 31);
            float4 kv = *(const float4*)(Kb + (size_t)(k0 + j) * HDIM + d4);
            Ks[idx + 0] = kv.x; Ks[idx + 1] = kv.y;
            Ks[idx + 2] = kv.z; Ks[idx + 3] = kv.w;
            float4 vv = *(const float4*)(Vb + (size_t)(k0 + j) * HDIM + d4);
            Vs[idx + 0] = vv.x; Vs[idx + 1] = vv.y;
            Vs[idx + 2] = vv.z; Vs[idx + 3] = vv.w;
        }
        __syncthreads();

        // scores for TK keys (full dot via quad shuffle-reduce)
        float s[TK];
        float tile_max = -1e30f;
#pragma unroll
        for (int j = 0; j < TK; ++j) {
            const float* kp = Ks + quad * QSTRIDE + j * 32;
            float d = 0.f;
#pragma unroll
            for (int i = 0; i < 32; ++i) d = fmaf(qreg[i], kp[i], d);
            d += __shfl_xor_sync(0xffffffffu, d, 1);
            d += __shfl_xor_sync(0xffffffffu, d, 2);
            s[j] = d;
            tile_max = fmaxf(tile_max, d);
        }

        // online softmax update
        float m_new = fmaxf(m_i, tile_max);
        float corr  = __expf(m_i - m_new);
        l_i *= corr;
#pragma unroll
        for (int i = 0; i < 32; ++i) acc[i] *= corr;

#pragma unroll
        for (int j = 0; j < TK; ++j) {
            float p = __expf(s[j] - m_new);
            l_i += p;
            const float* vp = Vs + quad * QSTRIDE + j * 32;
#pragma unroll
            for (int i = 0; i < 32; ++i) acc[i] = fmaf(p, vp[i], acc[i]);
        }
        m_i = m_new;
    }

    // epilogue: normalize and store into [B,S,H] layout
    float inv = 1.f / l_i;
    float* orow = O + ((size_t)b * SEQ + (q0 + qi)) * HID + h * HDIM + quad * 32;
#pragma unroll
    for (int i = 0; i < 32; i += 4) {
        float4 t;
        t.x = acc[i + 0] * inv;
        t.y = acc[i + 1] * inv;
        t.z = acc[i + 2] * inv;
        t.w = acc[i + 3] * inv;
        *(float4*)(orow + i) = t;
    }
}

// ---------------------------------------------------------------------------
// kernel_launch
// inputs (metadata order): x, Wq, bq, Wk, bk, Wv, bv, Wo, bo
// ---------------------------------------------------------------------------
extern "C" void kernel_launch(void* const* d_in, const int* in_sizes, int n_in,
                              void* d_out, int out_size)
{
    const float* x  = (const float*)d_in[0];
    const float* Wq = (const float*)d_in[1];
    const float* bq = (const float*)d_in[2];
    const float* Wk = (const float*)d_in[3];
    const float* bk = (const float*)d_in[4];
    const float* Wv = (const float*)d_in[5];
    const float* bv = (const float*)d_in[6];
    const float* Wo = (const float*)d_in[7];
    const float* bo = (const float*)d_in[8];
    float* out = (float*)d_out;

    void *qp, *kp, *vp, *cp;
    cudaGetSymbolAddress(&qp, g_q);
    cudaGetSymbolAddress(&kp, g_k);
    cudaGetSymbolAddress(&vp, g_v);
    cudaGetSymbolAddress(&cp, g_ctx);

    dim3 gg(HID / 128, MTOT / 128);   // (16, 32)
    dim3 gb(256);

    gemm_nt_bias<true ><<<gg, gb>>>(x, Wq, bq, (float*)qp, MTOT, HID, HID);
    gemm_nt_bias<true ><<<gg, gb>>>(x, Wk, bk, (float*)kp, MTOT, HID, HID);
    gemm_nt_bias<true ><<<gg, gb>>>(x, Wv, bv, (float*)vp, MTOT, HID, HID);

    dim3 ga(SEQ / TQ, BATCH * NHEADS);  // (32, 32)
    attn_kernel<<<ga, gb>>>((const float*)qp, (const float*)kp,
                            (const float*)vp, (float*)cp);

    gemm_nt_bias<false><<<gg, gb>>>((const float*)cp, Wo, bo, out, MTOT, HID, HID);
}

// round 2
// speedup vs baseline: 1.5572x; 1.5572x over previous
#include <cuda_runtime.h>
#include <cuda_bf16.h>
#include <mma.h>
#include <math.h>

using namespace nvcuda;

// Problem constants
#define HID    2048
#define NHEADS 16
#define HDIM   128
#define BATCH  2
#define SEQ    2048
#define MTOT   (BATCH*SEQ)   // 4096

// ---------------------------------------------------------------------------
// Scratch (device globals: allocation-free)
// ---------------------------------------------------------------------------
__device__ float g_q  [(size_t)MTOT * HID];   // [B,NH,S,HD]
__device__ float g_k  [(size_t)MTOT * HID];   // [B,NH,S,HD]
__device__ float g_v  [(size_t)MTOT * HID];   // [B,NH,S,HD]
__device__ float g_ctx[(size_t)MTOT * HID];   // [B,S,H]

// ---------------------------------------------------------------------------
// TF32 NT GEMM with bias:  C[m,n] = sum_k A[m,k]*B[n,k] + bias[n]
// A: [M,K] row-major, B: [N,K] row-major  (torch Linear: x @ W.T + b)
// wmma m16n16k8 tf32. Block tile 128x128, BK=32, 8 warps (4x2), each warp
// computes 32x64 via 2x4 fragments. Bias pre-loaded into accumulators via a
// replicated smem tile. Epilogue stores fragments directly to global:
//   SCATTER=false: row stride N
//   SCATTER=true : [B,NH,S,HD] layout; warp tiles are 64-col aligned so they
//                  never cross a head boundary -> plain ldm=HDIM store.
// ---------------------------------------------------------------------------
template<bool SCATTER>
__global__ void __launch_bounds__(256, 2)
gemm_tf32_bias(const float* __restrict__ A,
               const float* __restrict__ B,
               const float* __restrict__ bias,
               float* __restrict__ C,
               int M, int N, int K)
{
    constexpr int BM = 128, BN = 128, BK = 32;
    constexpr int LDT = BK + 4;              // 36 floats, 16B-aligned fragment rows

    __shared__ float smem[2 * BM * LDT];     // 36 KB
    float* As = smem;                        // [128][36]
    float* Bs = smem + BM * LDT;             // [128][36]

    const int tid = threadIdx.x;
    const int wid = tid >> 5;
    const int block_m = blockIdx.y * BM;
    const int block_n = blockIdx.x * BN;
    const int wm = (wid & 3) * 32;           // warp row offset in tile
    const int wn = (wid >> 2) * 64;          // warp col offset in tile

    wmma::fragment<wmma::accumulator, 16, 16, 8, float> fc[2][4];

    // ---- bias -> accumulators (replicated 16-row smem tile) ----
    {
        float* bias_s = smem;                // [16][132]
        for (int idx = tid; idx < 16 * 132; idx += 256) {
            int c = idx % 132;
            bias_s[idx] = (c < 128) ? bias[block_n + c] : 0.f;
        }
        __syncthreads();
#pragma unroll
        for (int i = 0; i < 2; ++i)
#pragma unroll
            for (int j = 0; j < 4; ++j)
                wmma::load_matrix_sync(fc[i][j], bias_s + wn + j * 16, 132,
                                       wmma::mem_row_major);
        __syncthreads();
    }

    const float* Ap = A + (size_t)block_m * K;
    const float* Bp = B + (size_t)block_n * K;
    const int lr = tid >> 3;                 // 0..31
    const int lc = (tid & 7) * 4;            // 0..28

    for (int k0 = 0; k0 < K; k0 += BK) {
        // load 128x32 of A and B, convert to tf32 on smem store
#pragma unroll
        for (int p = 0; p < 4; ++p) {
            int r = p * 32 + lr;
            float4 a = *(const float4*)(Ap + (size_t)r * K + k0 + lc);
            float* da = As + r * LDT + lc;
            da[0] = wmma::__float_to_tf32(a.x);
            da[1] = wmma::__float_to_tf32(a.y);
            da[2] = wmma::__float_to_tf32(a.z);
            da[3] = wmma::__float_to_tf32(a.w);
            float4 b = *(const float4*)(Bp + (size_t)r * K + k0 + lc);
            float* db = Bs + r * LDT + lc;
            db[0] = wmma::__float_to_tf32(b.x);
            db[1] = wmma::__float_to_tf32(b.y);
            db[2] = wmma::__float_to_tf32(b.z);
            db[3] = wmma::__float_to_tf32(b.w);
        }
        __syncthreads();

#pragma unroll
        for (int kk = 0; kk < BK; kk += 8) {
            wmma::fragment<wmma::matrix_a, 16, 16, 8, wmma::precision::tf32,
                           wmma::row_major> fa[2];
            wmma::fragment<wmma::matrix_b, 16, 16, 8, wmma::precision::tf32,
                           wmma::col_major> fb[4];
#pragma unroll
            for (int i = 0; i < 2; ++i)
                wmma::load_matrix_sync(fa[i], As + (wm + i * 16) * LDT + kk, LDT);
#pragma unroll
            for (int j = 0; j < 4; ++j)
                wmma::load_matrix_sync(fb[j], Bs + (wn + j * 16) * LDT + kk, LDT);
#pragma unroll
            for (int i = 0; i < 2; ++i)
#pragma unroll
                for (int j = 0; j < 4; ++j)
                    wmma::mma_sync(fc[i][j], fa[i], fb[j], fc[i][j]);
        }
        __syncthreads();
    }

    // ---- epilogue: direct global stores ----
#pragma unroll
    for (int i = 0; i < 2; ++i) {
#pragma unroll
        for (int j = 0; j < 4; ++j) {
            int m0 = block_m + wm + i * 16;
            int n0 = block_n + wn + j * 16;
            if (!SCATTER) {
                wmma::store_matrix_sync(C + (size_t)m0 * N + n0, fc[i][j], N,
                                        wmma::mem_row_major);
            } else {
                int b = m0 / SEQ, s = m0 - b * SEQ;     // 16 rows stay in one batch
                int h = n0 >> 7, d = n0 & 127;          // 16 cols stay in one head
                float* dst = C + (((size_t)b * NHEADS + h) * SEQ + s) * HDIM + d;
                wmma::store_matrix_sync(dst, fc[i][j], HDIM, wmma::mem_row_major);
            }
        }
    }
}

// ---------------------------------------------------------------------------
// Flash attention (fp32, online softmax), 2 queries per thread.
// grid: (SEQ/TQ, BATCH*NHEADS), block 256.
// Thread t: qi = t>>2 handles queries (qi, qi+64); quad = t&3 owns 32 d-dims.
// Each K/V smem element read feeds BOTH queries -> 0.5 LDS per FMA.
// K/V smem quad-swizzled: stride QSTRIDE between d-quads keeps the 4 quads of
// a warp in distinct banks (QSTRIDE % 32 == 8).
// ---------------------------------------------------------------------------
#define TQ 128
#define TK 16
#define QSTRIDE (TK * 32 + 8)   // 520

__global__ void __launch_bounds__(256, 1)
attn_kernel(const float* __restrict__ Q,
            const float* __restrict__ K,
            const float* __restrict__ V,
            float* __restrict__ O)
{
    __shared__ float Ks[4 * QSTRIDE];
    __shared__ float Vs[4 * QSTRIDE];

    const int bh = blockIdx.y;
    const int b  = bh / NHEADS;
    const int h  = bh - b * NHEADS;
    const int q0 = blockIdx.x * TQ;

    const int tid  = threadIdx.x;
    const int qi   = tid >> 2;            // 0..63
    const int quad = tid & 3;             // 0..3

    const float* Qb = Q + (size_t)bh * SEQ * HDIM;
    const float* Kb = K + (size_t)bh * SEQ * HDIM;
    const float* Vb = V + (size_t)bh * SEQ * HDIM;

    const float scale = 0.08838834764831845f;  // 1/sqrt(128)
    float qr0[32], qr1[32];
    {
        const float* p0 = Qb + (size_t)(q0 + qi) * HDIM + quad * 32;
        const float* p1 = Qb + (size_t)(q0 + qi + 64) * HDIM + quad * 32;
#pragma unroll
        for (int i = 0; i < 32; i += 4) {
            float4 t0 = *(const float4*)(p0 + i);
            qr0[i+0] = t0.x * scale; qr0[i+1] = t0.y * scale;
            qr0[i+2] = t0.z * scale; qr0[i+3] = t0.w * scale;
            float4 t1 = *(const float4*)(p1 + i);
            qr1[i+0] = t1.x * scale; qr1[i+1] = t1.y * scale;
            qr1[i+2] = t1.z * scale; qr1[i+3] = t1.w * scale;
        }
    }

    float acc0[32], acc1[32];
#pragma unroll
    for (int i = 0; i < 32; ++i) { acc0[i] = 0.f; acc1[i] = 0.f; }
    float m0 = -1e30f, l0 = 0.f;
    float m1 = -1e30f, l1 = 0.f;

    for (int k0 = 0; k0 < SEQ; k0 += TK) {
        __syncthreads();
        // cooperative load of K/V tile (TK x 128) into swizzled smem
        for (int f = tid; f < TK * 32; f += 256) {
            int j  = f >> 5;
            int d4 = (f & 31) * 4;
            int idx = (d4 >> 5) * QSTRIDE + j * 32 + (d4 & 31);
            float4 kv = *(const float4*)(Kb + (size_t)(k0 + j) * HDIM + d4);
            Ks[idx+0] = kv.x; Ks[idx+1] = kv.y; Ks[idx+2] = kv.z; Ks[idx+3] = kv.w;
            float4 vv = *(const float4*)(Vb + (size_t)(k0 + j) * HDIM + d4);
            Vs[idx+0] = vv.x; Vs[idx+1] = vv.y; Vs[idx+2] = vv.z; Vs[idx+3] = vv.w;
        }
        __syncthreads();

        // scores for TK keys, both queries (shared K read)
        float s0[TK], s1[TK];
        float tmax0 = -1e30f, tmax1 = -1e30f;
#pragma unroll
        for (int j = 0; j < TK; ++j) {
            const float* kp = Ks + quad * QSTRIDE + j * 32;
            float d0 = 0.f, d1 = 0.f;
#pragma unroll
            for (int i = 0; i < 32; ++i) {
                float kv = kp[i];
                d0 = fmaf(qr0[i], kv, d0);
                d1 = fmaf(qr1[i], kv, d1);
            }
            d0 += __shfl_xor_sync(0xffffffffu, d0, 1);
            d0 += __shfl_xor_sync(0xffffffffu, d0, 2);
            d1 += __shfl_xor_sync(0xffffffffu, d1, 1);
            d1 += __shfl_xor_sync(0xffffffffu, d1, 2);
            s0[j] = d0; tmax0 = fmaxf(tmax0, d0);
            s1[j] = d1; tmax1 = fmaxf(tmax1, d1);
        }

        // online softmax updates
        float mn0 = fmaxf(m0, tmax0);
        float mn1 = fmaxf(m1, tmax1);
        float c0 = __expf(m0 - mn0);
        float c1 = __expf(m1 - mn1);
        l0 *= c0; l1 *= c1;
#pragma unroll
        for (int i = 0; i < 32; ++i) { acc0[i] *= c0; acc1[i] *= c1; }
#pragma unroll
        for (int j = 0; j < TK; ++j) {
            s0[j] = __expf(s0[j] - mn0); l0 += s0[j];
            s1[j] = __expf(s1[j] - mn1); l1 += s1[j];
        }
        m0 = mn0; m1 = mn1;

        // V accumulate, both queries (shared V read)
#pragma unroll
        for (int j = 0; j < TK; ++j) {
            const float* vp = Vs + quad * QSTRIDE + j * 32;
            float p0 = s0[j], p1 = s1[j];
#pragma unroll
            for (int i = 0; i < 32; ++i) {
                float vv = vp[i];
                acc0[i] = fmaf(p0, vv, acc0[i]);
                acc1[i] = fmaf(p1, vv, acc1[i]);
            }
        }
    }

    // epilogue: normalize and store into [B,S,H] layout
    float inv0 = 1.f / l0, inv1 = 1.f / l1;
    float* o0 = O + ((size_t)b * SEQ + (q0 + qi))      * HID + h * HDIM + quad * 32;
    float* o1 = O + ((size_t)b * SEQ + (q0 + qi + 64)) * HID + h * HDIM + quad * 32;
#pragma unroll
    for (int i = 0; i < 32; i += 4) {
        float4 t0 = { acc0[i]*inv0, acc0[i+1]*inv0, acc0[i+2]*inv0, acc0[i+3]*inv0 };
        *(float4*)(o0 + i) = t0;
        float4 t1 = { acc1[i]*inv1, acc1[i+1]*inv1, acc1[i+2]*inv1, acc1[i+3]*inv1 };
        *(float4*)(o1 + i) = t1;
    }
}

// ---------------------------------------------------------------------------
// kernel_launch — inputs: x, Wq, bq, Wk, bk, Wv, bv, Wo, bo
// ---------------------------------------------------------------------------
extern "C" void kernel_launch(void* const* d_in, const int* in_sizes, int n_in,
                              void* d_out, int out_size)
{
    const float* x  = (const float*)d_in[0];
    const float* Wq = (const float*)d_in[1];
    const float* bq = (const float*)d_in[2];
    const float* Wk = (const float*)d_in[3];
    const float* bk = (const float*)d_in[4];
    const float* Wv = (const float*)d_in[5];
    const float* bv = (const float*)d_in[6];
    const float* Wo = (const float*)d_in[7];
    const float* bo = (const float*)d_in[8];
    float* out = (float*)d_out;

    void *qp, *kp, *vp, *cp;
    cudaGetSymbolAddress(&qp, g_q);
    cudaGetSymbolAddress(&kp, g_k);
    cudaGetSymbolAddress(&vp, g_v);
    cudaGetSymbolAddress(&cp, g_ctx);

    dim3 gg(HID / 128, MTOT / 128);   // (16, 32)
    dim3 gb(256);

    gemm_tf32_bias<true ><<<gg, gb>>>(x, Wq, bq, (float*)qp, MTOT, HID, HID);
    gemm_tf32_bias<true ><<<gg, gb>>>(x, Wk, bk, (float*)kp, MTOT, HID, HID);
    gemm_tf32_bias<true ><<<gg, gb>>>(x, Wv, bv, (float*)vp, MTOT, HID, HID);

    dim3 ga(SEQ / TQ, BATCH * NHEADS);  // (16, 32)
    attn_kernel<<<ga, gb>>>((const float*)qp, (const float*)kp,
                            (const float*)vp, (float*)cp);

    gemm_tf32_bias<false><<<gg, gb>>>((const float*)cp, Wo, bo, out, MTOT, HID, HID);
}

// round 4
// speedup vs baseline: 3.1924x; 2.0500x over previous
#include <cuda_runtime.h>
#include <cuda_bf16.h>
#include <mma.h>
#include <math.h>
#include <stdint.h>

using namespace nvcuda;

// Problem constants
#define HID    2048
#define NHEADS 16
#define HDIM   128
#define BATCH  2
#define SEQ    2048
#define MTOT   (BATCH*SEQ)   // 4096

// ---------------------------------------------------------------------------
// Scratch (device globals: allocation-free)
// ---------------------------------------------------------------------------
__device__ float g_q  [(size_t)MTOT * HID];   // [B,NH,S,HD] tf32-rounded
__device__ float g_k  [(size_t)MTOT * HID];   // [B,NH,S,HD] tf32-rounded
__device__ float g_v  [(size_t)MTOT * HID];   // [B,NH,S,HD] tf32-rounded
__device__ float g_ctx[(size_t)MTOT * HID];   // [B,S,H]     tf32-rounded
__device__ float g_xr [(size_t)MTOT * HID];   // x rounded to tf32
__device__ float g_wq [(size_t)HID * HID];    // weights rounded to tf32
__device__ float g_wk [(size_t)HID * HID];
__device__ float g_wv [(size_t)HID * HID];
__device__ float g_wo [(size_t)HID * HID];

// ---------------------------------------------------------------------------
// Helpers
// ---------------------------------------------------------------------------
__device__ __forceinline__ unsigned f2tf(float f) {
    unsigned u;
    asm("cvt.rna.tf32.f32 %0, %1;" : "=r"(u) : "f"(f));
    return u;
}
__device__ __forceinline__ float tf32r(float f) {
    return __uint_as_float(f2tf(f));
}
__device__ __forceinline__ void mma_tf32(float c[4], const unsigned a[4],
                                         unsigned b0, unsigned b1) {
    asm("mma.sync.aligned.m16n8k8.row.col.f32.tf32.tf32.f32 "
        "{%0,%1,%2,%3},{%4,%5,%6,%7},{%8,%9},{%0,%1,%2,%3};"
        : "+f"(c[0]), "+f"(c[1]), "+f"(c[2]), "+f"(c[3])
        : "r"(a[0]), "r"(a[1]), "r"(a[2]), "r"(a[3]), "r"(b0), "r"(b1));
}
__device__ __forceinline__ void cp16(uint32_t dst, const void* src) {
    asm volatile("cp.async.ca.shared.global [%0], [%1], 16;" :: "r"(dst), "l"(src));
}
__device__ __forceinline__ void cp_commit() {
    asm volatile("cp.async.commit_group;");
}
__device__ __forceinline__ void cp_wait0() {
    asm volatile("cp.async.wait_group 0;");
}
__device__ __forceinline__ void cp_wait1() {
    asm volatile("cp.async.wait_group 1;");
}

// ---------------------------------------------------------------------------
// Elementwise round-to-tf32 (RN) kernel. n must be a multiple of 4.
// ---------------------------------------------------------------------------
__global__ void round_tf32_kernel(const float* __restrict__ in,
                                  float* __restrict__ out, int n4)
{
    int i = blockIdx.x * blockDim.x + threadIdx.x;
    if (i < n4) {
        float4 v = ((const float4*)in)[i];
        v.x = tf32r(v.x); v.y = tf32r(v.y);
        v.z = tf32r(v.z); v.w = tf32r(v.w);
        ((float4*)out)[i] = v;
    }
}

// ---------------------------------------------------------------------------
// TF32 NT GEMM with bias, cp.async double-buffered.
//   C[m,n] = sum_k A[m,k]*B[n,k] + bias[n]
// A: [M,K] row-major (tf32-rounded), B: [N,K] row-major (tf32-rounded).
// Tile 128x256, BK=16, 256 threads, 8 warps each 64x64 (4x4 wmma frags).
// SCATTER=true: write into [B,NH,S,HD] layout, rounding values to tf32.
// Dynamic smem: 2 stages * (128*20 + 256*20) floats = 61440 B.
// ---------------------------------------------------------------------------
#define G_BM 128
#define G_BN 256
#define G_BK 16
#define G_LDA 20                       // BK + 4 pad
#define G_ASTG (G_BM * G_LDA)          // 2560 floats per A stage
#define G_BSTG (G_BN * G_LDA)          // 5120 floats per B stage
#define G_SMEM_BYTES (2 * (G_ASTG + G_BSTG) * 4)   // 61440

template<bool SCATTER>
__global__ void __launch_bounds__(256, 1)
gemm_tf32_pipe(const float* __restrict__ A,
               const float* __restrict__ B,
               const float* __restrict__ bias,
               float* __restrict__ C,
               int M, int N, int K)
{
    extern __shared__ float smem[];
    float* sA = smem;                  // [2][128][20]
    float* sB = smem + 2 * G_ASTG;     // [2][256][20]

    const int tid = threadIdx.x;
    const int wid = tid >> 5;
    const int block_m = blockIdx.y * G_BM;
    const int block_n = blockIdx.x * G_BN;
    const int wm = (wid & 1) * 64;     // warp row offset
    const int wn = (wid >> 1) * 64;    // warp col offset

    wmma::fragment<wmma::accumulator, 16, 16, 8, float> fc[4][4];

    // ---- bias -> accumulators via replicated smem tile [16][260] ----
    {
        float* bias_s = smem;
        for (int idx = tid; idx < 16 * 260; idx += 256) {
            int c = idx % 260;
            bias_s[idx] = (c < G_BN) ? bias[block_n + c] : 0.f;
        }
        __syncthreads();
#pragma unroll
        for (int i = 0; i < 4; ++i)
#pragma unroll
            for (int j = 0; j < 4; ++j)
                wmma::load_matrix_sync(fc[i][j], bias_s + wn + j * 16, 260,
                                       wmma::mem_row_major);
        __syncthreads();
    }

    const float* Ap = A + (size_t)block_m * K;
    const float* Bp = B + (size_t)block_n * K;

    uint32_t sA_u = (uint32_t)__cvta_generic_to_shared(sA);
    uint32_t sB_u = (uint32_t)__cvta_generic_to_shared(sB);

    const int NSTAGE = K / G_BK;       // 128

    // prologue: stage 0 into buffer 0
    {
#pragma unroll
        for (int i = 0; i < 2; ++i) {
            int idx = tid + i * 256;
            int r = idx >> 2;
            cp16(sA_u + (r * G_LDA + (idx & 3) * 4) * 4,
                 Ap + (size_t)r * K + (idx & 3) * 4);
        }
#pragma unroll
        for (int i = 0; i < 4; ++i) {
            int idx = tid + i * 256;
            int r = idx >> 2;
            cp16(sB_u + (r * G_LDA + (idx & 3) * 4) * 4,
                 Bp + (size_t)r * K + (idx & 3) * 4);
        }
        cp_commit();
    }

    for (int t = 0; t < NSTAGE; ++t) {
        int buf = t & 1;
        if (t + 1 < NSTAGE) {
            int nbuf = (t + 1) & 1;
            int k0 = (t + 1) * G_BK;
#pragma unroll
            for (int i = 0; i < 2; ++i) {
                int idx = tid + i * 256;
                int r = idx >> 2;
                cp16(sA_u + (nbuf * G_ASTG + r * G_LDA + (idx & 3) * 4) * 4,
                     Ap + (size_t)r * K + k0 + (idx & 3) * 4);
            }
#pragma unroll
            for (int i = 0; i < 4; ++i) {
                int idx = tid + i * 256;
                int r = idx >> 2;
                cp16(sB_u + (nbuf * G_BSTG + r * G_LDA + (idx & 3) * 4) * 4,
                     Bp + (size_t)r * K + k0 + (idx & 3) * 4);
            }
            cp_commit();
            cp_wait1();
        } else {
            cp_wait0();
        }
        __syncthreads();

        const float* cA = sA + buf * G_ASTG;
        const float* cB = sB + buf * G_BSTG;
#pragma unroll
        for (int kk = 0; kk < G_BK; kk += 8) {
            wmma::fragment<wmma::matrix_a, 16, 16, 8, wmma::precision::tf32,
                           wmma::row_major> fa[4];
            wmma::fragment<wmma::matrix_b, 16, 16, 8, wmma::precision::tf32,
                           wmma::col_major> fb[4];
#pragma unroll
            for (int i = 0; i < 4; ++i)
                wmma::load_matrix_sync(fa[i], cA + (wm + i * 16) * G_LDA + kk, G_LDA);
#pragma unroll
            for (int j = 0; j < 4; ++j)
                wmma::load_matrix_sync(fb[j], cB + (wn + j * 16) * G_LDA + kk, G_LDA);
#pragma unroll
            for (int i = 0; i < 4; ++i)
#pragma unroll
                for (int j = 0; j < 4; ++j)
                    wmma::mma_sync(fc[i][j], fa[i], fb[j], fc[i][j]);
        }
        __syncthreads();
    }

    // ---- epilogue ----
#pragma unroll
    for (int i = 0; i < 4; ++i) {
#pragma unroll
        for (int j = 0; j < 4; ++j) {
            int m0 = block_m + wm + i * 16;
            int n0 = block_n + wn + j * 16;
            if (!SCATTER) {
                wmma::store_matrix_sync(C + (size_t)m0 * N + n0, fc[i][j], N,
                                        wmma::mem_row_major);
            } else {
                // round to tf32 (consumer is tensor-core attention)
#pragma unroll
                for (int e = 0; e < fc[i][j].num_elements; ++e)
                    fc[i][j].x[e] = tf32r(fc[i][j].x[e]);
                int b = m0 / SEQ, s = m0 - b * SEQ;
                int h = n0 >> 7, d = n0 & 127;
                float* dst = C + (((size_t)b * NHEADS + h) * SEQ + s) * HDIM + d;
                wmma::store_matrix_sync(dst, fc[i][j], HDIM, wmma::mem_row_major);
            }
        }
    }
}

// ---------------------------------------------------------------------------
// Flash attention, mma.sync tf32 (FA2 style).
// Block: 256 threads (8 warps). TQ=128 queries (16 rows per warp), TK=64 keys.
// Q held as persistent A-fragments in registers. K/V double-buffered cp.async.
// S computed in m16n8k8 C-fragment layout; softmax done in-register (rows are
// lane/4 and lane/4+8); P staged through per-warp smem tile, then PV mma.
// All inputs tf32-rounded by producers; output rounded for the O-projection.
// Dynamic smem: K 2*64*132 + V 2*64*136 + P 8*16*68 = 43008 floats = 172032 B.
// ---------------------------------------------------------------------------
#define A_TK 64
#define A_LDK 132
#define A_LDV 136
#define A_LDP 68
#define A_KSTG (A_TK * A_LDK)             // 8448
#define A_VSTG (A_TK * A_LDV)             // 8704
#define A_SMEM_FLOATS (2*A_KSTG + 2*A_VSTG + 8*16*A_LDP)  // 43008
#define A_SMEM_BYTES (A_SMEM_FLOATS * 4)                   // 172032

__global__ void __launch_bounds__(256, 1)
attn_mma_kernel(const float* __restrict__ Q,
                const float* __restrict__ K,
                const float* __restrict__ V,
                float* __restrict__ O)
{
    extern __shared__ float smem[];
    float* sK = smem;                     // [2][64][132]
    float* sV = smem + 2 * A_KSTG;        // [2][64][136]
    float* sP = sV + 2 * A_VSTG;          // [8][16][68]

    const int tid  = threadIdx.x;
    const int wid  = tid >> 5;
    const int lane = tid & 31;
    const int r0   = lane >> 2;           // fragment row group 0..7
    const int cq   = lane & 3;            // fragment col group 0..3

    const int bh = blockIdx.y;            // 0..B*NH-1
    const int b  = bh / NHEADS;
    const int h  = bh - b * NHEADS;
    const int q0 = blockIdx.x * 128;      // query tile base
    const int wr = wid * 16;              // warp's row offset within tile

    const float* Qb = Q + ((size_t)bh * SEQ + q0 + wr) * HDIM;
    const float* Kb = K + (size_t)bh * SEQ * HDIM;
    const float* Vb = V + (size_t)bh * SEQ * HDIM;

    // ---- load Q fragments (persistent): aq[ks][4], scaled by 1/sqrt(128) ----
    const float scale = 0.08838834764831845f;
    unsigned aq[16][4];
#pragma unroll
    for (int ks = 0; ks < 16; ++ks) {
        aq[ks][0] = f2tf(scale * Qb[(size_t)(r0)     * HDIM + ks * 8 + cq]);
        aq[ks][1] = f2tf(scale * Qb[(size_t)(r0 + 8) * HDIM + ks * 8 + cq]);
        aq[ks][2] = f2tf(scale * Qb[(size_t)(r0)     * HDIM + ks * 8 + cq + 4]);
        aq[ks][3] = f2tf(scale * Qb[(size_t)(r0 + 8) * HDIM + ks * 8 + cq + 4]);
    }

    float oc[16][4];
#pragma unroll
    for (int i = 0; i < 16; ++i)
#pragma unroll
        for (int j = 0; j < 4; ++j) oc[i][j] = 0.f;
    float m0 = -1e30f, l0 = 0.f;
    float m1 = -1e30f, l1 = 0.f;

    uint32_t sK_u = (uint32_t)__cvta_generic_to_shared(sK);
    uint32_t sV_u = (uint32_t)__cvta_generic_to_shared(sV);
    float* Pw = sP + wid * 16 * A_LDP;

    const int NT = SEQ / A_TK;            // 32

    // prologue: tile 0 -> buffer 0
    {
#pragma unroll
        for (int i = 0; i < 8; ++i) {
            int idx = tid + i * 256;
            int r = idx >> 5, c = (idx & 31) * 4;
            cp16(sK_u + (r * A_LDK + c) * 4, Kb + (size_t)r * HDIM + c);
            cp16(sV_u + (r * A_LDV + c) * 4, Vb + (size_t)r * HDIM + c);
        }
        cp_commit();
    }

    for (int t = 0; t < NT; ++t) {
        int buf = t & 1;
        if (t + 1 < NT) {
            int nbuf = (t + 1) & 1;
            const float* Kn = Kb + (size_t)(t + 1) * A_TK * HDIM;
            const float* Vn = Vb + (size_t)(t + 1) * A_TK * HDIM;
#pragma unroll
            for (int i = 0; i < 8; ++i) {
                int idx = tid + i * 256;
                int r = idx >> 5, c = (idx & 31) * 4;
                cp16(sK_u + (nbuf * A_KSTG + r * A_LDK + c) * 4,
                     Kn + (size_t)r * HDIM + c);
                cp16(sV_u + (nbuf * A_VSTG + r * A_LDV + c) * 4,
                     Vn + (size_t)r * HDIM + c);
            }
            cp_commit();
            cp_wait1();
        } else {
            cp_wait0();
        }
        __syncthreads();

        const float* cK = sK + buf * A_KSTG;
        const float* cV = sV + buf * A_VSTG;

        // ---- S = Q @ K^T for this 128x64 tile (per warp: 16x64) ----
        float sc[8][4];
#pragma unroll
        for (int nt = 0; nt < 8; ++nt)
#pragma unroll
            for (int j = 0; j < 4; ++j) sc[nt][j] = 0.f;

#pragma unroll
        for (int ks = 0; ks < 16; ++ks) {
#pragma unroll
            for (int nt = 0; nt < 8; ++nt) {
                const float* kp = cK + (nt * 8 + r0) * A_LDK + ks * 8 + cq;
                unsigned b0 = __float_as_uint(kp[0]);
                unsigned b1 = __float_as_uint(kp[4]);
                mma_tf32(sc[nt], aq[ks], b0, b1);
            }
        }

        // ---- online softmax (rows r0 and r0+8 of this warp) ----
        float tmax0 = -1e30f, tmax1 = -1e30f;
#pragma unroll
        for (int nt = 0; nt < 8; ++nt) {
            tmax0 = fmaxf(tmax0, fmaxf(sc[nt][0], sc[nt][1]));
            tmax1 = fmaxf(tmax1, fmaxf(sc[nt][2], sc[nt][3]));
        }
        tmax0 = fmaxf(tmax0, __shfl_xor_sync(0xffffffffu, tmax0, 1));
        tmax0 = fmaxf(tmax0, __shfl_xor_sync(0xffffffffu, tmax0, 2));
        tmax1 = fmaxf(tmax1, __shfl_xor_sync(0xffffffffu, tmax1, 1));
        tmax1 = fmaxf(tmax1, __shfl_xor_sync(0xffffffffu, tmax1, 2));

        float m0n = fmaxf(m0, tmax0);
        float m1n = fmaxf(m1, tmax1);
        float c0 = __expf(m0 - m0n);
        float c1 = __expf(m1 - m1n);
        m0 = m0n; m1 = m1n;

        float ls0 = 0.f, ls1 = 0.f;
#pragma unroll
        for (int nt = 0; nt < 8; ++nt) {
            sc[nt][0] = tf32r(__expf(sc[nt][0] - m0n));
            sc[nt][1] = tf32r(__expf(sc[nt][1] - m0n));
            sc[nt][2] = tf32r(__expf(sc[nt][2] - m1n));
            sc[nt][3] = tf32r(__expf(sc[nt][3] - m1n));
            ls0 += sc[nt][0] + sc[nt][1];
            ls1 += sc[nt][2] + sc[nt][3];
        }
        ls0 += __shfl_xor_sync(0xffffffffu, ls0, 1);
        ls0 += __shfl_xor_sync(0xffffffffu, ls0, 2);
        ls1 += __shfl_xor_sync(0xffffffffu, ls1, 1);
        ls1 += __shfl_xor_sync(0xffffffffu, ls1, 2);
        l0 = l0 * c0 + ls0;
        l1 = l1 * c1 + ls1;

        // rescale output accumulators
#pragma unroll
        for (int nt = 0; nt < 16; ++nt) {
            oc[nt][0] *= c0; oc[nt][1] *= c0;
            oc[nt][2] *= c1; oc[nt][3] *= c1;
        }

        // ---- stage P to per-warp smem ----
#pragma unroll
        for (int nt = 0; nt < 8; ++nt) {
            float2 p01 = make_float2(sc[nt][0], sc[nt][1]);
            float2 p23 = make_float2(sc[nt][2], sc[nt][3]);
            *(float2*)(Pw + (size_t)r0 * A_LDP + nt * 8 + 2 * cq) = p01;
            *(float2*)(Pw + (size_t)(r0 + 8) * A_LDP + nt * 8 + 2 * cq) = p23;
        }
        __syncwarp();

        // ---- O += P @ V  (16x64 @ 64x128) ----
#pragma unroll
        for (int ks2 = 0; ks2 < 8; ++ks2) {
            unsigned pa[4];
            pa[0] = __float_as_uint(Pw[(size_t)r0 * A_LDP + ks2 * 8 + cq]);
            pa[1] = __float_as_uint(Pw[(size_t)(r0 + 8) * A_LDP + ks2 * 8 + cq]);
            pa[2] = __float_as_uint(Pw[(size_t)r0 * A_LDP + ks2 * 8 + cq + 4]);
            pa[3] = __float_as_uint(Pw[(size_t)(r0 + 8) * A_LDP + ks2 * 8 + cq + 4]);
#pragma unroll
            for (int nt2 = 0; nt2 < 16; ++nt2) {
                const float* vp = cV + (ks2 * 8 + cq) * A_LDV + nt2 * 8 + r0;
                unsigned b0 = __float_as_uint(vp[0]);
                unsigned b1 = __float_as_uint(vp[4 * A_LDV]);
                mma_tf32(oc[nt2], pa, b0, b1);
            }
        }
        __syncwarp();
        __syncthreads();
    }

    // ---- epilogue: normalize, round to tf32, store into [B,S,H] ----
    float inv0 = 1.f / l0;
    float inv1 = 1.f / l1;
    int row0 = q0 + wr + r0;
    int row1 = row0 + 8;
    float* out0 = O + ((size_t)b * SEQ + row0) * HID + h * HDIM;
    float* out1 = O + ((size_t)b * SEQ + row1) * HID + h * HDIM;
#pragma unroll
    for (int nt2 = 0; nt2 < 16; ++nt2) {
        int col = nt2 * 8 + 2 * cq;
        float2 v0 = make_float2(tf32r(oc[nt2][0] * inv0), tf32r(oc[nt2][1] * inv0));
        float2 v1 = make_float2(tf32r(oc[nt2][2] * inv1), tf32r(oc[nt2][3] * inv1));
        *(float2*)(out0 + col) = v0;
        *(float2*)(out1 + col) = v1;
    }
}

// ---------------------------------------------------------------------------
// kernel_launch — inputs: x, Wq, bq, Wk, bk, Wv, bv, Wo, bo
// Deterministic, no static state; cudaFuncSetAttribute is idempotent and not
// a stream operation (capture-safe).
// ---------------------------------------------------------------------------
extern "C" void kernel_launch(void* const* d_in, const int* in_sizes, int n_in,
                              void* d_out, int out_size)
{
    const float* x  = (const float*)d_in[0];
    const float* Wq = (const float*)d_in[1];
    const float* bq = (const float*)d_in[2];
    const float* Wk = (const float*)d_in[3];
    const float* bk = (const float*)d_in[4];
    const float* Wv = (const float*)d_in[5];
    const float* bv = (const float*)d_in[6];
    const float* Wo = (const float*)d_in[7];
    const float* bo = (const float*)d_in[8];
    float* out = (float*)d_out;

    void *qp, *kp, *vp, *cp, *xrp, *wqp, *wkp, *wvp, *wop;
    cudaGetSymbolAddress(&qp,  g_q);
    cudaGetSymbolAddress(&kp,  g_k);
    cudaGetSymbolAddress(&vp,  g_v);
    cudaGetSymbolAddress(&cp,  g_ctx);
    cudaGetSymbolAddress(&xrp, g_xr);
    cudaGetSymbolAddress(&wqp, g_wq);
    cudaGetSymbolAddress(&wkp, g_wk);
    cudaGetSymbolAddress(&wvp, g_wv);
    cudaGetSymbolAddress(&wop, g_wo);

    cudaFuncSetAttribute(gemm_tf32_pipe<true>,
                         cudaFuncAttributeMaxDynamicSharedMemorySize, G_SMEM_BYTES);
    cudaFuncSetAttribute(gemm_tf32_pipe<false>,
                         cudaFuncAttributeMaxDynamicSharedMemorySize, G_SMEM_BYTES);
    cudaFuncSetAttribute(attn_mma_kernel,
                         cudaFuncAttributeMaxDynamicSharedMemorySize, A_SMEM_BYTES);

    // pre-round inputs to tf32 (RN)
    {
        int nx4 = MTOT * HID / 4;       // 2M
        int nw4 = HID * HID / 4;        // 1M
        round_tf32_kernel<<<(nx4 + 255) / 256, 256>>>(x,  (float*)xrp, nx4);
        round_tf32_kernel<<<(nw4 + 255) / 256, 256>>>(Wq, (float*)wqp, nw4);
        round_tf32_kernel<<<(nw4 + 255) / 256, 256>>>(Wk, (float*)wkp, nw4);
        round_tf32_kernel<<<(nw4 + 255) / 256, 256>>>(Wv, (float*)wvp, nw4);
        round_tf32_kernel<<<(nw4 + 255) / 256, 256>>>(Wo, (float*)wop, nw4);
    }

    dim3 gg(HID / G_BN, MTOT / G_BM);   // (8, 32)
    dim3 gb(256);

    gemm_tf32_pipe<true ><<<gg, gb, G_SMEM_BYTES>>>((const float*)xrp, (const float*)wqp, bq, (float*)qp, MTOT, HID, HID);
    gemm_tf32_pipe<true ><<<gg, gb, G_SMEM_BYTES>>>((const float*)xrp, (const float*)wkp, bk, (float*)kp, MTOT, HID, HID);
    gemm_tf32_pipe<true ><<<gg, gb, G_SMEM_BYTES>>>((const float*)xrp, (const float*)wvp, bv, (float*)vp, MTOT, HID, HID);

    dim3 ga(SEQ / 128, BATCH * NHEADS); // (16, 32)
    attn_mma_kernel<<<ga, gb, A_SMEM_BYTES>>>((const float*)qp, (const float*)kp,
                                              (const float*)vp, (float*)cp);

    gemm_tf32_pipe<false><<<gg, gb, G_SMEM_BYTES>>>((const float*)cp, (const float*)wop, bo, out, MTOT, HID, HID);
}

// round 6
// speedup vs baseline: 5.5281x; 1.7317x over previous
#include <cuda_runtime.h>
#include <cuda_bf16.h>
#include <math.h>
#include <stdint.h>

// Problem constants
#define HID    2048
#define NHEADS 16
#define HDIM   128
#define BATCH  2
#define SEQ    2048
#define MTOT   (BATCH*SEQ)   // 4096

// ---------------------------------------------------------------------------
// Scratch (device globals: allocation-free)
// ---------------------------------------------------------------------------
__device__ float g_q  [(size_t)MTOT * HID];   // [B,NH,S,HD] tf32-rounded
__device__ float g_k  [(size_t)MTOT * HID];   // [B,NH,S,HD] tf32-rounded
__device__ float g_v  [(size_t)MTOT * HID];   // [B,NH,S,HD] tf32-rounded
__device__ float g_ctx[(size_t)MTOT * HID];   // [B,S,H]     tf32-rounded
__device__ float g_xr [(size_t)MTOT * HID];   // x rounded to tf32
__device__ float g_wq [(size_t)HID * HID];    // weights rounded to tf32
__device__ float g_wk [(size_t)HID * HID];
__device__ float g_wv [(size_t)HID * HID];
__device__ float g_wo [(size_t)HID * HID];

// ---------------------------------------------------------------------------
// Helpers
// ---------------------------------------------------------------------------
__device__ __forceinline__ unsigned f2tf(float f) {
    unsigned u;
    asm("cvt.rna.tf32.f32 %0, %1;" : "=r"(u) : "f"(f));
    return u;
}
__device__ __forceinline__ float tf32r(float f) {
    return __uint_as_float(f2tf(f));
}
__device__ __forceinline__ void mma_tf32(float c[4], const unsigned a[4],
                                         unsigned b0, unsigned b1) {
    asm("mma.sync.aligned.m16n8k8.row.col.f32.tf32.tf32.f32 "
        "{%0,%1,%2,%3},{%4,%5,%6,%7},{%8,%9},{%0,%1,%2,%3};"
        : "+f"(c[0]), "+f"(c[1]), "+f"(c[2]), "+f"(c[3])
        : "r"(a[0]), "r"(a[1]), "r"(a[2]), "r"(a[3]), "r"(b0), "r"(b1));
}
__device__ __forceinline__ void cp16(uint32_t dst, const void* src) {
    asm volatile("cp.async.ca.shared.global [%0], [%1], 16;" :: "r"(dst), "l"(src));
}
__device__ __forceinline__ void cp_commit() {
    asm volatile("cp.async.commit_group;");
}
__device__ __forceinline__ void cp_wait0() {
    asm volatile("cp.async.wait_group 0;");
}
__device__ __forceinline__ void cp_wait1() {
    asm volatile("cp.async.wait_group 1;");
}

// ---------------------------------------------------------------------------
// Elementwise round-to-tf32 (RN) kernel. n must be a multiple of 4.
// ---------------------------------------------------------------------------
__global__ void round_tf32_kernel(const float* __restrict__ in,
                                  float* __restrict__ out, int n4)
{
    int i = blockIdx.x * blockDim.x + threadIdx.x;
    if (i < n4) {
        float4 v = ((const float4*)in)[i];
        v.x = tf32r(v.x); v.y = tf32r(v.y);
        v.z = tf32r(v.z); v.w = tf32r(v.w);
        ((float4*)out)[i] = v;
    }
}

// ---------------------------------------------------------------------------
// Raw mma.sync TF32 NT GEMM with bias, 3-stage cp.async ring.
//   C[m,n] = sum_k A[m,k]*B[n,k] + bias[n]
// A: [M,K] row-major (tf32-rounded), B: [N,K] row-major (tf32-rounded).
// Block tile 128x256, BK=32, 256 threads / 8 warps (2x4), warp tile 64x64
// (4 m-frags x 8 n-frags of m16n8k8). LD=36 pad: fragment LDS lane address
// r0*4 + cq is a bijection onto banks 0..31 -> conflict-free.
// ONE __syncthreads per stage: wait -> sync -> issue(t+2) -> compute(t).
// SCATTER=true: write into [B,NH,S,HD] layout with tf32-RN rounding.
// ---------------------------------------------------------------------------
#define G_BM 128
#define G_BN 256
#define G_BK 32
#define G_LD 36
#define G_AS (G_BM * G_LD)             // 4608 floats
#define G_BS (G_BN * G_LD)             // 9216 floats
#define G_STG (G_AS + G_BS)            // 13824 floats = 55296 B / stage
#define G_SMEM_BYTES (3 * G_STG * 4)   // 165888 B

template<bool SCATTER>
__global__ void __launch_bounds__(256, 1)
gemm_raw(const float* __restrict__ A,
         const float* __restrict__ B,
         const float* __restrict__ bias,
         float* __restrict__ C,
         int M, int N, int K)
{
    extern __shared__ float smem[];

    const int tid  = threadIdx.x;
    const int wid  = tid >> 5;
    const int lane = tid & 31;
    const int r0   = lane >> 2;        // 0..7
    const int cq   = lane & 3;         // 0..3

    const int block_m = blockIdx.y * G_BM;
    const int block_n = blockIdx.x * G_BN;
    const int wm = (wid & 1) * 64;     // warp row offset
    const int wn = (wid >> 1) * 64;    // warp col offset

    // accumulators, bias-initialized (bias depends only on column)
    float fc[4][8][4];
#pragma unroll
    for (int fn = 0; fn < 8; ++fn) {
        float b0v = bias[block_n + wn + fn * 8 + 2 * cq];
        float b1v = bias[block_n + wn + fn * 8 + 2 * cq + 1];
#pragma unroll
        for (int fm = 0; fm < 4; ++fm) {
            fc[fm][fn][0] = b0v; fc[fm][fn][1] = b1v;
            fc[fm][fn][2] = b0v; fc[fm][fn][3] = b1v;
        }
    }

    const float* Ap = A + (size_t)block_m * K;
    const float* Bp = B + (size_t)block_n * K;
    uint32_t sbase = (uint32_t)__cvta_generic_to_shared(smem);

    const int NS = K / G_BK;           // 64

    // cp.async of one stage: A 128x32 (4 chunks/thread), B 256x32 (8 chunks)
    auto issue = [&](int kt, int stg) {
        int k0 = kt * G_BK;
        uint32_t sb = sbase + (uint32_t)(stg * G_STG) * 4;
#pragma unroll
        for (int i = 0; i < 4; ++i) {
            int idx = tid + i * 256;
            int r = idx >> 3, c = (idx & 7) * 4;
            cp16(sb + (r * G_LD + c) * 4, Ap + (size_t)r * K + k0 + c);
        }
#pragma unroll
        for (int i = 0; i < 8; ++i) {
            int idx = tid + i * 256;
            int r = idx >> 3, c = (idx & 7) * 4;
            cp16(sb + (G_AS + r * G_LD + c) * 4, Bp + (size_t)r * K + k0 + c);
        }
        cp_commit();
    };

    issue(0, 0);
    issue(1, 1);

    for (int t = 0; t < NS; ++t) {
        if (t + 1 < NS) cp_wait1(); else cp_wait0();   // retire group t
        __syncthreads();                               // t's data visible to all
        if (t + 2 < NS) issue(t + 2, (t + 2) % 3);     // into buffer freed at t-1

        const float* sA = smem + (t % 3) * G_STG;
        const float* sB = sA + G_AS;

#pragma unroll
        for (int kk = 0; kk < G_BK; kk += 8) {
            unsigned a[4][4], b[8][2];
#pragma unroll
            for (int fm = 0; fm < 4; ++fm) {
                const float* ap = sA + (wm + fm * 16 + r0) * G_LD + kk + cq;
                a[fm][0] = __float_as_uint(ap[0]);
                a[fm][1] = __float_as_uint(ap[8 * G_LD]);
                a[fm][2] = __float_as_uint(ap[4]);
                a[fm][3] = __float_as_uint(ap[8 * G_LD + 4]);
            }
#pragma unroll
            for (int fn = 0; fn < 8; ++fn) {
                const float* bp = sB + (wn + fn * 8 + r0) * G_LD + kk + cq;
                b[fn][0] = __float_as_uint(bp[0]);
                b[fn][1] = __float_as_uint(bp[4]);
            }
#pragma unroll
            for (int fm = 0; fm < 4; ++fm)
#pragma unroll
                for (int fn = 0; fn < 8; ++fn)
                    mma_tf32(fc[fm][fn], a[fm], b[fn][0], b[fn][1]);
        }
        // no trailing sync: next iteration's issue targets the buffer being
        // computed now, but only after next iteration's __syncthreads.
    }

    // ---- epilogue: rows r0 / r0+8, cols 2cq / 2cq+1 per fragment ----
#pragma unroll
    for (int fm = 0; fm < 4; ++fm) {
#pragma unroll
        for (int fn = 0; fn < 8; ++fn) {
            int m0 = block_m + wm + fm * 16 + r0;
            int n0 = block_n + wn + fn * 8 + 2 * cq;
            float* c = fc[fm][fn];
            if (!SCATTER) {
                *(float2*)(C + (size_t)m0 * N + n0)       = make_float2(c[0], c[1]);
                *(float2*)(C + (size_t)(m0 + 8) * N + n0) = make_float2(c[2], c[3]);
            } else {
                int bb = m0 / SEQ, s = m0 - bb * SEQ;   // 16-row frag: same batch
                int h = n0 >> 7, d = n0 & 127;          // 8-col frag: same head
                float* dst0 = C + (((size_t)bb * NHEADS + h) * SEQ + s) * HDIM + d;
                *(float2*)dst0 = make_float2(tf32r(c[0]), tf32r(c[1]));
                *(float2*)(dst0 + 8 * HDIM) = make_float2(tf32r(c[2]), tf32r(c[3]));
            }
        }
    }
}

// ---------------------------------------------------------------------------
// Flash attention, mma.sync tf32 (FA2 style). UNCHANGED from R4 (proven).
// Block: 256 threads (8 warps). TQ=128 queries (16 rows per warp), TK=64 keys.
// ---------------------------------------------------------------------------
#define A_TK 64
#define A_LDK 132
#define A_LDV 136
#define A_LDP 68
#define A_KSTG (A_TK * A_LDK)             // 8448
#define A_VSTG (A_TK * A_LDV)             // 8704
#define A_SMEM_FLOATS (2*A_KSTG + 2*A_VSTG + 8*16*A_LDP)  // 43008
#define A_SMEM_BYTES (A_SMEM_FLOATS * 4)                   // 172032

__global__ void __launch_bounds__(256, 1)
attn_mma_kernel(const float* __restrict__ Q,
                const float* __restrict__ K,
                const float* __restrict__ V,
                float* __restrict__ O)
{
    extern __shared__ float smem[];
    float* sK = smem;                     // [2][64][132]
    float* sV = smem + 2 * A_KSTG;        // [2][64][136]
    float* sP = sV + 2 * A_VSTG;          // [8][16][68]

    const int tid  = threadIdx.x;
    const int wid  = tid >> 5;
    const int lane = tid & 31;
    const int r0   = lane >> 2;
    const int cq   = lane & 3;

    const int bh = blockIdx.y;
    const int b  = bh / NHEADS;
    const int h  = bh - b * NHEADS;
    const int q0 = blockIdx.x * 128;
    const int wr = wid * 16;

    const float* Qb = Q + ((size_t)bh * SEQ + q0 + wr) * HDIM;
    const float* Kb = K + (size_t)bh * SEQ * HDIM;
    const float* Vb = V + (size_t)bh * SEQ * HDIM;

    const float scale = 0.08838834764831845f;
    unsigned aq[16][4];
#pragma unroll
    for (int ks = 0; ks < 16; ++ks) {
        aq[ks][0] = f2tf(scale * Qb[(size_t)(r0)     * HDIM + ks * 8 + cq]);
        aq[ks][1] = f2tf(scale * Qb[(size_t)(r0 + 8) * HDIM + ks * 8 + cq]);
        aq[ks][2] = f2tf(scale * Qb[(size_t)(r0)     * HDIM + ks * 8 + cq + 4]);
        aq[ks][3] = f2tf(scale * Qb[(size_t)(r0 + 8) * HDIM + ks * 8 + cq + 4]);
    }

    float oc[16][4];
#pragma unroll
    for (int i = 0; i < 16; ++i)
#pragma unroll
        for (int j = 0; j < 4; ++j) oc[i][j] = 0.f;
    float m0 = -1e30f, l0 = 0.f;
    float m1 = -1e30f, l1 = 0.f;

    uint32_t sK_u = (uint32_t)__cvta_generic_to_shared(sK);
    uint32_t sV_u = (uint32_t)__cvta_generic_to_shared(sV);
    float* Pw = sP + wid * 16 * A_LDP;

    const int NT = SEQ / A_TK;            // 32

    {
#pragma unroll
        for (int i = 0; i < 8; ++i) {
            int idx = tid + i * 256;
            int r = idx >> 5, c = (idx & 31) * 4;
            cp16(sK_u + (r * A_LDK + c) * 4, Kb + (size_t)r * HDIM + c);
            cp16(sV_u + (r * A_LDV + c) * 4, Vb + (size_t)r * HDIM + c);
        }
        cp_commit();
    }

    for (int t = 0; t < NT; ++t) {
        int buf = t & 1;
        if (t + 1 < NT) {
            int nbuf = (t + 1) & 1;
            const float* Kn = Kb + (size_t)(t + 1) * A_TK * HDIM;
            const float* Vn = Vb + (size_t)(t + 1) * A_TK * HDIM;
#pragma unroll
            for (int i = 0; i < 8; ++i) {
                int idx = tid + i * 256;
                int r = idx >> 5, c = (idx & 31) * 4;
                cp16(sK_u + (nbuf * A_KSTG + r * A_LDK + c) * 4,
                     Kn + (size_t)r * HDIM + c);
                cp16(sV_u + (nbuf * A_VSTG + r * A_LDV + c) * 4,
                     Vn + (size_t)r * HDIM + c);
            }
            cp_commit();
            cp_wait1();
        } else {
            cp_wait0();
        }
        __syncthreads();

        const float* cK = sK + buf * A_KSTG;
        const float* cV = sV + buf * A_VSTG;

        // ---- S = Q @ K^T (per warp: 16x64) ----
        float sc[8][4];
#pragma unroll
        for (int nt = 0; nt < 8; ++nt)
#pragma unroll
            for (int j = 0; j < 4; ++j) sc[nt][j] = 0.f;

#pragma unroll
        for (int ks = 0; ks < 16; ++ks) {
#pragma unroll
            for (int nt = 0; nt < 8; ++nt) {
                const float* kp = cK + (nt * 8 + r0) * A_LDK + ks * 8 + cq;
                unsigned b0 = __float_as_uint(kp[0]);
                unsigned b1 = __float_as_uint(kp[4]);
                mma_tf32(sc[nt], aq[ks], b0, b1);
            }
        }

        // ---- online softmax ----
        float tmax0 = -1e30f, tmax1 = -1e30f;
#pragma unroll
        for (int nt = 0; nt < 8; ++nt) {
            tmax0 = fmaxf(tmax0, fmaxf(sc[nt][0], sc[nt][1]));
            tmax1 = fmaxf(tmax1, fmaxf(sc[nt][2], sc[nt][3]));
        }
        tmax0 = fmaxf(tmax0, __shfl_xor_sync(0xffffffffu, tmax0, 1));
        tmax0 = fmaxf(tmax0, __shfl_xor_sync(0xffffffffu, tmax0, 2));
        tmax1 = fmaxf(tmax1, __shfl_xor_sync(0xffffffffu, tmax1, 1));
        tmax1 = fmaxf(tmax1, __shfl_xor_sync(0xffffffffu, tmax1, 2));

        float m0n = fmaxf(m0, tmax0);
        float m1n = fmaxf(m1, tmax1);
        float c0 = __expf(m0 - m0n);
        float c1 = __expf(m1 - m1n);
        m0 = m0n; m1 = m1n;

        float ls0 = 0.f, ls1 = 0.f;
#pragma unroll
        for (int nt = 0; nt < 8; ++nt) {
            sc[nt][0] = tf32r(__expf(sc[nt][0] - m0n));
            sc[nt][1] = tf32r(__expf(sc[nt][1] - m0n));
            sc[nt][2] = tf32r(__expf(sc[nt][2] - m1n));
            sc[nt][3] = tf32r(__expf(sc[nt][3] - m1n));
            ls0 += sc[nt][0] + sc[nt][1];
            ls1 += sc[nt][2] + sc[nt][3];
        }
        ls0 += __shfl_xor_sync(0xffffffffu, ls0, 1);
        ls0 += __shfl_xor_sync(0xffffffffu, ls0, 2);
        ls1 += __shfl_xor_sync(0xffffffffu, ls1, 1);
        ls1 += __shfl_xor_sync(0xffffffffu, ls1, 2);
        l0 = l0 * c0 + ls0;
        l1 = l1 * c1 + ls1;

#pragma unroll
        for (int nt = 0; nt < 16; ++nt) {
            oc[nt][0] *= c0; oc[nt][1] *= c0;
            oc[nt][2] *= c1; oc[nt][3] *= c1;
        }

        // ---- stage P to per-warp smem ----
#pragma unroll
        for (int nt = 0; nt < 8; ++nt) {
            float2 p01 = make_float2(sc[nt][0], sc[nt][1]);
            float2 p23 = make_float2(sc[nt][2], sc[nt][3]);
            *(float2*)(Pw + (size_t)r0 * A_LDP + nt * 8 + 2 * cq) = p01;
            *(float2*)(Pw + (size_t)(r0 + 8) * A_LDP + nt * 8 + 2 * cq) = p23;
        }
        __syncwarp();

        // ---- O += P @ V ----
#pragma unroll
        for (int ks2 = 0; ks2 < 8; ++ks2) {
            unsigned pa[4];
            pa[0] = __float_as_uint(Pw[(size_t)r0 * A_LDP + ks2 * 8 + cq]);
            pa[1] = __float_as_uint(Pw[(size_t)(r0 + 8) * A_LDP + ks2 * 8 + cq]);
            pa[2] = __float_as_uint(Pw[(size_t)r0 * A_LDP + ks2 * 8 + cq + 4]);
            pa[3] = __float_as_uint(Pw[(size_t)(r0 + 8) * A_LDP + ks2 * 8 + cq + 4]);
#pragma unroll
            for (int nt2 = 0; nt2 < 16; ++nt2) {
                const float* vp = cV + (ks2 * 8 + cq) * A_LDV + nt2 * 8 + r0;
                unsigned b0 = __float_as_uint(vp[0]);
                unsigned b1 = __float_as_uint(vp[4 * A_LDV]);
                mma_tf32(oc[nt2], pa, b0, b1);
            }
        }
        __syncwarp();
        __syncthreads();
    }

    // ---- epilogue ----
    float inv0 = 1.f / l0;
    float inv1 = 1.f / l1;
    int row0 = q0 + wr + r0;
    int row1 = row0 + 8;
    float* out0 = O + ((size_t)b * SEQ + row0) * HID + h * HDIM;
    float* out1 = O + ((size_t)b * SEQ + row1) * HID + h * HDIM;
#pragma unroll
    for (int nt2 = 0; nt2 < 16; ++nt2) {
        int col = nt2 * 8 + 2 * cq;
        float2 v0 = make_float2(tf32r(oc[nt2][0] * inv0), tf32r(oc[nt2][1] * inv0));
        float2 v1 = make_float2(tf32r(oc[nt2][2] * inv1), tf32r(oc[nt2][3] * inv1));
        *(float2*)(out0 + col) = v0;
        *(float2*)(out1 + col) = v1;
    }
}

// ---------------------------------------------------------------------------
// kernel_launch — inputs: x, Wq, bq, Wk, bk, Wv, bv, Wo, bo
// Deterministic, no static state; cudaFuncSetAttribute is idempotent and not
// a stream operation (capture-safe).
// ---------------------------------------------------------------------------
extern "C" void kernel_launch(void* const* d_in, const int* in_sizes, int n_in,
                              void* d_out, int out_size)
{
    const float* x  = (const float*)d_in[0];
    const float* Wq = (const float*)d_in[1];
    const float* bq = (const float*)d_in[2];
    const float* Wk = (const float*)d_in[3];
    const float* bk = (const float*)d_in[4];
    const float* Wv = (const float*)d_in[5];
    const float* bv = (const float*)d_in[6];
    const float* Wo = (const float*)d_in[7];
    const float* bo = (const float*)d_in[8];
    float* out = (float*)d_out;

    void *qp, *kp, *vp, *cp, *xrp, *wqp, *wkp, *wvp, *wop;
    cudaGetSymbolAddress(&qp,  g_q);
    cudaGetSymbolAddress(&kp,  g_k);
    cudaGetSymbolAddress(&vp,  g_v);
    cudaGetSymbolAddress(&cp,  g_ctx);
    cudaGetSymbolAddress(&xrp, g_xr);
    cudaGetSymbolAddress(&wqp, g_wq);
    cudaGetSymbolAddress(&wkp, g_wk);
    cudaGetSymbolAddress(&wvp, g_wv);
    cudaGetSymbolAddress(&wop, g_wo);

    cudaFuncSetAttribute(gemm_raw<true>,
                         cudaFuncAttributeMaxDynamicSharedMemorySize, G_SMEM_BYTES);
    cudaFuncSetAttribute(gemm_raw<false>,
                         cudaFuncAttributeMaxDynamicSharedMemorySize, G_SMEM_BYTES);
    cudaFuncSetAttribute(attn_mma_kernel,
                         cudaFuncAttributeMaxDynamicSharedMemorySize, A_SMEM_BYTES);

    // pre-round inputs to tf32 (RN)
    {
        int nx4 = MTOT * HID / 4;
        int nw4 = HID * HID / 4;
        round_tf32_kernel<<<(nx4 + 255) / 256, 256>>>(x,  (float*)xrp, nx4);
        round_tf32_kernel<<<(nw4 + 255) / 256, 256>>>(Wq, (float*)wqp, nw4);
        round_tf32_kernel<<<(nw4 + 255) / 256, 256>>>(Wk, (float*)wkp, nw4);
        round_tf32_kernel<<<(nw4 + 255) / 256, 256>>>(Wv, (float*)wvp, nw4);
        round_tf32_kernel<<<(nw4 + 255) / 256, 256>>>(Wo, (float*)wop, nw4);
    }

    dim3 gg(HID / G_BN, MTOT / G_BM);   // (8, 32)
    dim3 gb(256);

    gemm_raw<true ><<<gg, gb, G_SMEM_BYTES>>>((const float*)xrp, (const float*)wqp, bq, (float*)qp, MTOT, HID, HID);
    gemm_raw<true ><<<gg, gb, G_SMEM_BYTES>>>((const float*)xrp, (const float*)wkp, bk, (float*)kp, MTOT, HID, HID);
    gemm_raw<true ><<<gg, gb, G_SMEM_BYTES>>>((const float*)xrp, (const float*)wvp, bv, (float*)vp, MTOT, HID, HID);

    dim3 ga(SEQ / 128, BATCH * NHEADS); // (16, 32)
    attn_mma_kernel<<<ga, gb, A_SMEM_BYTES>>>((const float*)qp, (const float*)kp,
                                              (const float*)vp, (float*)cp);

    gemm_raw<false><<<gg, gb, G_SMEM_BYTES>>>((const float*)cp, (const float*)wop, bo, out, MTOT, HID, HID);
}